// round 4
// baseline (speedup 1.0000x reference)
#include <cuda_runtime.h>
#include <cuda_bf16.h>
#include <cstdint>

// Problem constants
#define NB 8
#define NC 128
#define NHEADS 8
#define NN 16384            // H*W
#define HK 16               // channels per head
#define NBH 64              // NB*NHEADS

// Kernel-1 tiling
#define TN 256              // n-tile held in smem
#define PAD 260             // padded row stride (floats), multiple of 4 for float4
#define CHUNK1 1024         // n per CTA in kernel 1 -> grid.y = 16
#define NCHUNK1 (NN / CHUNK1)

// Kernel-2 tiling
#define CHUNK2 2048         // n per CTA in kernel 2 -> grid.y = 8
#define NCHUNK2 (NN / CHUNK2)

// Scratch: per-chunk PARTIAL context / exp-sums, owned slices, no atomics.
// g_Up element order within a chunk: [warp][lane] with
//   kk = (warp>>1)*4 + (lane>>3), vv = (warp&1)*8 + (lane&7)
__device__ float g_Up[NBH * NCHUNK1 * HK * HK];
__device__ float g_Sp[NBH * NCHUNK1 * HK];

// ---------------------------------------------------------------------------
// Kernel 1: per (b,h,chunk):
//   Up[kk][vv] = sum_{n in chunk} exp(k[kk,n]) * v[vv,n]
//   Sp[kk]     = sum_{n in chunk} exp(k[kk,n])
// grid = (64, 16), block = 256 (8 warps; warp w owns U subtile 4x8)
// ---------------------------------------------------------------------------
__global__ void __launch_bounds__(256)
context_kernel(const float* __restrict__ x1, const float* __restrict__ x2) {
    __shared__ __align__(16) float e_s[HK * PAD];
    __shared__ __align__(16) float v_s[HK * PAD];

    const int tid   = threadIdx.x;
    const int bh    = blockIdx.x;
    const int chunk = blockIdx.y;
    const int warp  = tid >> 5;
    const int lane  = tid & 31;

    // load-phase mapping: 64 threads per row (float4), 4 rows per pass
    const int lrow = tid >> 6;          // 0..3
    const int lcol = (tid & 63) << 2;   // 0..252 step 4

    // compute-phase: warp w owns rows kk0..kk0+3, cols vv0..vv0+7 of U;
    // lanes index n (consecutive -> conflict-free LDS)
    const int kk0 = (warp >> 1) << 2;
    const int vv0 = (warp & 1) << 3;

    const float* kb = x2 + (size_t)bh * HK * NN;
    const float* vb = x1 + (size_t)bh * HK * NN;

    float acc[4][8];
#pragma unroll
    for (int i = 0; i < 4; i++)
#pragma unroll
        for (int l = 0; l < 8; l++) acc[i][l] = 0.f;

    float sS0 = 0.f, sS1 = 0.f;   // warp w accumulates rows 2w, 2w+1 of S

    const int n_start = chunk * CHUNK1;

    for (int t = 0; t < CHUNK1 / TN; t++) {
        const int n0 = n_start + t * TN;

        // ---- load tile with float4: 4 rows per pass, 4 passes ----
#pragma unroll
        for (int p = 0; p < 4; p++) {
            const int r = lrow + 4 * p;
            float4 kv = *reinterpret_cast<const float4*>(&kb[(size_t)r * NN + n0 + lcol]);
            float4 vv = *reinterpret_cast<const float4*>(&vb[(size_t)r * NN + n0 + lcol]);
            float4 ev;
            ev.x = __expf(kv.x); ev.y = __expf(kv.y);
            ev.z = __expf(kv.z); ev.w = __expf(kv.w);
            *reinterpret_cast<float4*>(&e_s[r * PAD + lcol]) = ev;
            *reinterpret_cast<float4*>(&v_s[r * PAD + lcol]) = vv;
        }
        __syncthreads();

        // ---- S partial sums (warp w: rows 2w and 2w+1; lane-consecutive) ----
        {
            float s0 = 0.f, s1 = 0.f;
#pragma unroll
            for (int c = 0; c < TN / 32; c++) {
                s0 += e_s[(2 * warp) * PAD + lane + c * 32];
                s1 += e_s[(2 * warp + 1) * PAD + lane + c * 32];
            }
            sS0 += s0; sS1 += s1;
        }

        // ---- GEMM: lane = n (conflict-free), 8 n-steps of 32 ----
#pragma unroll
        for (int j = 0; j < TN / 32; j++) {
            const int n = j * 32 + lane;
            float ee[4], vvr[8];
#pragma unroll
            for (int i = 0; i < 4; i++) ee[i]  = e_s[(kk0 + i) * PAD + n];
#pragma unroll
            for (int l = 0; l < 8; l++) vvr[l] = v_s[(vv0 + l) * PAD + n];
#pragma unroll
            for (int i = 0; i < 4; i++)
#pragma unroll
                for (int l = 0; l < 8; l++)
                    acc[i][l] += ee[i] * vvr[l];
        }
        __syncthreads();   // protect smem before next tile's loads
    }

    // ---- S warp reduction -> owned global slice ----
#pragma unroll
    for (int off = 16; off > 0; off >>= 1) {
        sS0 += __shfl_down_sync(0xFFFFFFFFu, sS0, off);
        sS1 += __shfl_down_sync(0xFFFFFFFFu, sS1, off);
    }
    if (lane == 0) {
        g_Sp[(bh * NCHUNK1 + chunk) * HK + 2 * warp]     = sS0;
        g_Sp[(bh * NCHUNK1 + chunk) * HK + 2 * warp + 1] = sS1;
    }

    // ---- warp-reduce acc over lanes; lane e ends holding element e ----
    float outv = 0.f;
#pragma unroll
    for (int e = 0; e < 32; e++) {
        float v = acc[e >> 3][e & 7];
#pragma unroll
        for (int off = 16; off > 0; off >>= 1)
            v += __shfl_xor_sync(0xFFFFFFFFu, v, off);
        if (lane == e) outv = v;
    }
    g_Up[(bh * NCHUNK1 + chunk) * (HK * HK) + warp * 32 + lane] = outv;
}

// ---------------------------------------------------------------------------
// Kernel 2: reduce partials -> C; then per n:
//   q_sm = softmax_kk(k[:,n]);  out[vv,n] = sum_kk C[kk][vv]*q_sm[kk]
// grid = (64, 8), block = 256; each thread handles 2 contiguous n per iter.
// ---------------------------------------------------------------------------
__global__ void __launch_bounds__(256, 3)
attend_kernel(const float* __restrict__ x2, float* __restrict__ out) {
    __shared__ float C_s[HK * HK];
    __shared__ float S_s[HK];

    const int tid = threadIdx.x;
    const int bh  = blockIdx.x;

    // ---- reduce S partials (threads 0..15) ----
    if (tid < HK) {
        float s = 0.f;
#pragma unroll
        for (int c = 0; c < NCHUNK1; c++)
            s += g_Sp[(bh * NCHUNK1 + c) * HK + tid];
        S_s[tid] = s;
    }

    // ---- reduce U partials over chunks (each thread owns one element) ----
    float u = 0.f;
#pragma unroll
    for (int c = 0; c < NCHUNK1; c++)
        u += g_Up[(bh * NCHUNK1 + c) * (HK * HK) + tid];

    // element (warp,lane) order -> (kk, vv)
    const int w  = tid >> 5, l = tid & 31;
    const int kk = ((w >> 1) << 2) + (l >> 3);
    const int vv = ((w & 1) << 3) + (l & 7);

    __syncthreads();
    C_s[kk * HK + vv] = u / S_s[kk];
    __syncthreads();

    const float* kb = x2 + (size_t)bh * HK * NN;
    float*       ob = out + (size_t)bh * HK * NN;

    const int base0 = blockIdx.y * CHUNK2;

    // each iter covers 512 n (256 threads x 2), CHUNK2/512 = 4 iters
    for (int base = base0; base < base0 + CHUNK2; base += 512) {
        const int n0 = base + (tid << 1);

        // ---- load q[16] as float2 (16 independent LDG.64, MLP=16) ----
        float2 q[HK];
#pragma unroll
        for (int c = 0; c < HK; c++)
            q[c] = *reinterpret_cast<const float2*>(&kb[(size_t)c * NN + n0]);

        // ---- 16-channel softmax over channels, per lane of the float2 ----
        float mx = q[0].x, my = q[0].y;
#pragma unroll
        for (int c = 1; c < HK; c++) {
            mx = fmaxf(mx, q[c].x);
            my = fmaxf(my, q[c].y);
        }
        float sx = 0.f, sy = 0.f;
#pragma unroll
        for (int c = 0; c < HK; c++) {
            q[c].x = __expf(q[c].x - mx); sx += q[c].x;
            q[c].y = __expf(q[c].y - my); sy += q[c].y;
        }
        const float rx = 1.f / sx, ry = 1.f / sy;

        // ---- out[vv] = (sum_kk C[kk][vv] * e[kk]) * r ; store immediately ----
#pragma unroll
        for (int ov = 0; ov < HK; ov++) {
            float ox = 0.f, oy = 0.f;
#pragma unroll
            for (int c = 0; c < HK; c++) {
                const float cc = C_s[c * HK + ov];   // uniform -> smem broadcast
                ox += cc * q[c].x;
                oy += cc * q[c].y;
            }
            float2 o = make_float2(ox * rx, oy * ry);
            *reinterpret_cast<float2*>(&ob[(size_t)ov * NN + n0]) = o;
        }
    }
}

// ---------------------------------------------------------------------------
extern "C" void kernel_launch(void* const* d_in, const int* in_sizes, int n_in,
                              void* d_out, int out_size) {
    const float* x1 = (const float*)d_in[0];   // values
    const float* x2 = (const float*)d_in[1];   // keys/queries
    float* out = (float*)d_out;

    dim3 grid1(NBH, NCHUNK1);
    context_kernel<<<grid1, 256>>>(x1, x2);

    dim3 grid2(NBH, NCHUNK2);
    attend_kernel<<<grid2, 256>>>(x2, out);
}

// round 5
// speedup vs baseline: 1.4446x; 1.4446x over previous
#include <cuda_runtime.h>
#include <cuda_bf16.h>
#include <cstdint>

// Problem constants
#define NB 8
#define NC 128
#define NHEADS 8
#define NN 16384            // H*W
#define HK 16               // channels per head
#define NBH 64              // NB*NHEADS

// Kernel-1 tiling
#define TN 256              // n-tile held in smem
#define PAD 260             // padded row stride (floats), multiple of 4 for float4
#define CHUNK1 1024         // n per CTA in kernel 1 -> grid.y = 16
#define NCHUNK1 (NN / CHUNK1)

// Kernel-2 tiling
#define CHUNK2 2048         // n per CTA in kernel 2 -> grid.y = 8
#define NCHUNK2 (NN / CHUNK2)

// Scratch: per-chunk PARTIAL context / exp-sums, owned slices, no atomics.
// g_Up element order within a chunk: [warp][lane] with
//   kk = (warp>>1)*4 + (lane>>3), vv = (warp&1)*8 + (lane&7)
__device__ float g_Up[NBH * NCHUNK1 * HK * HK];
__device__ float g_Sp[NBH * NCHUNK1 * HK];

// ---------------------------------------------------------------------------
// Kernel 1: per (b,h,chunk):
//   Up[kk][vv] = sum_{n in chunk} exp(k[kk,n]) * v[vv,n]
//   Sp[kk]     = sum_{n in chunk} exp(k[kk,n])
// grid = (64, 16), block = 256 (8 warps; warp w owns a 4x8 U-subtile).
// Software-pipelined: next tile's global loads are prefetched into registers
// before computing on the current SMEM tile.
// ---------------------------------------------------------------------------
__global__ void __launch_bounds__(256)
context_kernel(const float* __restrict__ x1, const float* __restrict__ x2) {
    __shared__ __align__(16) float e_s[HK * PAD];
    __shared__ __align__(16) float v_s[HK * PAD];

    const int tid   = threadIdx.x;
    const int bh    = blockIdx.x;
    const int chunk = blockIdx.y;
    const int warp  = tid >> 5;
    const int lane  = tid & 31;

    // load-phase mapping: 64 threads per row (float4), 4 rows per pass
    const int lrow = tid >> 6;          // 0..3
    const int lcol = (tid & 63) << 2;   // 0..252 step 4

    // compute-phase: warp w owns rows kk0..kk0+3, cols vv0..vv0+7 of U;
    // lanes index n (consecutive -> conflict-free LDS)
    const int kk0 = (warp >> 1) << 2;
    const int vv0 = (warp & 1) << 3;

    const float* kb = x2 + (size_t)bh * HK * NN;
    const float* vb = x1 + (size_t)bh * HK * NN;

    float acc[4][8];
#pragma unroll
    for (int i = 0; i < 4; i++)
#pragma unroll
        for (int l = 0; l < 8; l++) acc[i][l] = 0.f;

    float sS0 = 0.f, sS1 = 0.f;   // warp w accumulates rows 2w, 2w+1 of S

    const int n_start = chunk * CHUNK1;

    // ---- prefetch tile 0 into registers ----
    float4 pk[4], pv[4];
#pragma unroll
    for (int p = 0; p < 4; p++) {
        const int r = lrow + 4 * p;
        pk[p] = *reinterpret_cast<const float4*>(&kb[(size_t)r * NN + n_start + lcol]);
        pv[p] = *reinterpret_cast<const float4*>(&vb[(size_t)r * NN + n_start + lcol]);
    }

    for (int t = 0; t < CHUNK1 / TN; t++) {
        // ---- commit prefetched tile to smem (exp applied to k) ----
#pragma unroll
        for (int p = 0; p < 4; p++) {
            const int r = lrow + 4 * p;
            float4 ev;
            ev.x = __expf(pk[p].x); ev.y = __expf(pk[p].y);
            ev.z = __expf(pk[p].z); ev.w = __expf(pk[p].w);
            *reinterpret_cast<float4*>(&e_s[r * PAD + lcol]) = ev;
            *reinterpret_cast<float4*>(&v_s[r * PAD + lcol]) = pv[p];
        }
        __syncthreads();

        // ---- issue next tile's global loads (latency overlaps compute) ----
        if (t + 1 < CHUNK1 / TN) {
            const int n1 = n_start + (t + 1) * TN;
#pragma unroll
            for (int p = 0; p < 4; p++) {
                const int r = lrow + 4 * p;
                pk[p] = *reinterpret_cast<const float4*>(&kb[(size_t)r * NN + n1 + lcol]);
                pv[p] = *reinterpret_cast<const float4*>(&vb[(size_t)r * NN + n1 + lcol]);
            }
        }

        // ---- S partial sums (warp w: rows 2w and 2w+1; lane-consecutive) ----
        {
            float s0 = 0.f, s1 = 0.f;
#pragma unroll
            for (int c = 0; c < TN / 32; c++) {
                s0 += e_s[(2 * warp) * PAD + lane + c * 32];
                s1 += e_s[(2 * warp + 1) * PAD + lane + c * 32];
            }
            sS0 += s0; sS1 += s1;
        }

        // ---- GEMM: lane = n (conflict-free), 8 n-steps of 32 ----
#pragma unroll
        for (int j = 0; j < TN / 32; j++) {
            const int n = j * 32 + lane;
            float ee[4], vvr[8];
#pragma unroll
            for (int i = 0; i < 4; i++) ee[i]  = e_s[(kk0 + i) * PAD + n];
#pragma unroll
            for (int l = 0; l < 8; l++) vvr[l] = v_s[(vv0 + l) * PAD + n];
#pragma unroll
            for (int i = 0; i < 4; i++)
#pragma unroll
                for (int l = 0; l < 8; l++)
                    acc[i][l] += ee[i] * vvr[l];
        }
        __syncthreads();   // protect smem before next commit
    }

    // ---- S warp reduction -> owned global slice ----
#pragma unroll
    for (int off = 16; off > 0; off >>= 1) {
        sS0 += __shfl_down_sync(0xFFFFFFFFu, sS0, off);
        sS1 += __shfl_down_sync(0xFFFFFFFFu, sS1, off);
    }
    if (lane == 0) {
        g_Sp[(bh * NCHUNK1 + chunk) * HK + 2 * warp]     = sS0;
        g_Sp[(bh * NCHUNK1 + chunk) * HK + 2 * warp + 1] = sS1;
    }

    // ---- warp-reduce acc over lanes; lane e ends holding element e ----
    float outv = 0.f;
#pragma unroll
    for (int e = 0; e < 32; e++) {
        float v = acc[e >> 3][e & 7];
#pragma unroll
        for (int off = 16; off > 0; off >>= 1)
            v += __shfl_xor_sync(0xFFFFFFFFu, v, off);
        if (lane == e) outv = v;
    }
    g_Up[(bh * NCHUNK1 + chunk) * (HK * HK) + warp * 32 + lane] = outv;
}

// ---------------------------------------------------------------------------
// Kernel 2: reduce partials -> C; then per n:
//   q_sm = softmax_kk(k[:,n]);  out[vv,n] = sum_kk C[kk][vv]*q_sm[kk]
// grid = (64, 8), block = 256; each thread handles 2 contiguous n per iter.
// launch_bounds(256,2): 128-reg budget — enough headroom to avoid spills.
// ---------------------------------------------------------------------------
__global__ void __launch_bounds__(256, 2)
attend_kernel(const float* __restrict__ x2, float* __restrict__ out) {
    __shared__ float C_s[HK * HK];
    __shared__ float S_s[HK];

    const int tid = threadIdx.x;
    const int bh  = blockIdx.x;

    // ---- reduce S partials (threads 0..15) ----
    if (tid < HK) {
        float s = 0.f;
#pragma unroll
        for (int c = 0; c < NCHUNK1; c++)
            s += g_Sp[(bh * NCHUNK1 + c) * HK + tid];
        S_s[tid] = s;
    }

    // ---- reduce U partials over chunks (each thread owns one element) ----
    float u = 0.f;
#pragma unroll
    for (int c = 0; c < NCHUNK1; c++)
        u += g_Up[(bh * NCHUNK1 + c) * (HK * HK) + tid];

    // element (warp,lane) order -> (kk, vv)
    const int w  = tid >> 5, l = tid & 31;
    const int kk = ((w >> 1) << 2) + (l >> 3);
    const int vv = ((w & 1) << 3) + (l & 7);

    __syncthreads();
    C_s[kk * HK + vv] = u / S_s[kk];
    __syncthreads();

    const float* kb = x2 + (size_t)bh * HK * NN;
    float*       ob = out + (size_t)bh * HK * NN;

    const int base0 = blockIdx.y * CHUNK2;

    // each iter covers 512 n (256 threads x 2), CHUNK2/512 = 4 iters
    for (int base = base0; base < base0 + CHUNK2; base += 512) {
        const int n0 = base + (tid << 1);

        // ---- load q[16] as float2 (16 independent LDG.64, MLP=16) ----
        float2 q[HK];
#pragma unroll
        for (int c = 0; c < HK; c++)
            q[c] = *reinterpret_cast<const float2*>(&kb[(size_t)c * NN + n0]);

        // ---- 16-channel softmax over channels, per lane of the float2 ----
        float mx = q[0].x, my = q[0].y;
#pragma unroll
        for (int c = 1; c < HK; c++) {
            mx = fmaxf(mx, q[c].x);
            my = fmaxf(my, q[c].y);
        }
        float sx = 0.f, sy = 0.f;
#pragma unroll
        for (int c = 0; c < HK; c++) {
            q[c].x = __expf(q[c].x - mx); sx += q[c].x;
            q[c].y = __expf(q[c].y - my); sy += q[c].y;
        }
        const float rx = 1.f / sx, ry = 1.f / sy;

        // ---- out[vv] = (sum_kk C[kk][vv] * e[kk]) * r ; store immediately ----
#pragma unroll
        for (int ov = 0; ov < HK; ov++) {
            float ox = 0.f, oy = 0.f;
#pragma unroll
            for (int c = 0; c < HK; c++) {
                const float cc = C_s[c * HK + ov];   // uniform -> smem broadcast
                ox += cc * q[c].x;
                oy += cc * q[c].y;
            }
            float2 o = make_float2(ox * rx, oy * ry);
            *reinterpret_cast<float2*>(&ob[(size_t)ov * NN + n0]) = o;
        }
    }
}

// ---------------------------------------------------------------------------
extern "C" void kernel_launch(void* const* d_in, const int* in_sizes, int n_in,
                              void* d_out, int out_size) {
    const float* x1 = (const float*)d_in[0];   // values
    const float* x2 = (const float*)d_in[1];   // keys/queries
    float* out = (float*)d_out;

    dim3 grid1(NBH, NCHUNK1);
    context_kernel<<<grid1, 256>>>(x1, x2);

    dim3 grid2(NBH, NCHUNK2);
    attend_kernel<<<grid2, 256>>>(x2, out);
}